// round 12
// baseline (speedup 1.0000x reference)
#include <cuda_runtime.h>
#include <cuda_bf16.h>

#define BATCH 8
#define CH    3
#define TT    16
#define H     512
#define WID   512
#define S     224
#define RMAXF 1024.0f

#define PLANES_PER_B (CH * TT)
#define P 3
#define HWPLANE (H * WID)
#define SSPLANE (S * S)
#define PLB  (HWPLANE * 4)         // plane stride, bytes (LDG imm)
#define ROWB (WID * 4)             // row stride, bytes
#define OPLB (SSPLANE * 4)         // out plane stride, bytes

// R10 memory shape (4 LDG.64 + 1 STG.64 per plane-pair, immediates off one
// base pointer) with TWO pair-slots' loads batched per phase for 2x MLP.
// Slots per phase: j, j+32; phase 0 covers pairs 0..63, phase 1 covers
// 64..111 (second slot half-predicated). 64-reg budget, occ ~50%.
__global__ __launch_bounds__(256, 4) void crop_prompter_kernel(
    const float* __restrict__ x,
    const int*   __restrict__ cam_views,
    const float* __restrict__ resize,
    const float* __restrict__ yoffs,
    const float* __restrict__ xoffs,
    float*       __restrict__ out)
{
    const int group  = blockIdx.z;
    const int plane0 = group * P;
    const int b      = group / (PLANES_PER_B / P);
    const int tx     = threadIdx.x;
    const int ty     = threadIdx.y;

    const int   cam   = __ldg(&cam_views[b]);
    const float r     = floorf(fminf(fmaxf(__ldg(&resize[cam]), (float)H), RMAXF));
    const float scale = (float)H / r;          // in [0.5, 1.0]
    const float yo    = floorf(fminf(fmaxf(__ldg(&yoffs[cam]), 0.0f), r - (float)S));
    const float xo    = floorf(fminf(fmaxf(__ldg(&xoffs[cam]), 0.0f), r - (float)S));

    const int ys = blockIdx.y * 8 + ty;
    const float sy = fmaxf((yo + (float)ys + 0.5f) * scale - 0.5f, 0.0f);
    const int   y0 = (int)sy;                  // <= 254 given input bounds
    const float wy = sy - (float)y0, onewy = 1.0f - wy;

    const char* __restrict__ pbase =
        (const char*)(x + (size_t)plane0 * HWPLANE + (size_t)y0 * WID);
    char* __restrict__ obase =
        (char*)(out + (size_t)plane0 * SSPLANE + (size_t)ys * S);

    const float base = (xo + 0.5f) * scale - 0.5f;

    #pragma unroll
    for (int half = 0; half < 2; ++half) {
        const int j0 = tx + 64 * half;         // always < 112
        const int j1 = j0 + 32;                // phase1: active only tx<16
        const bool act1 = (j1 < S / 2);

        // ---- index math, slot 0 ----
        const float rawa0 = fmaf((float)(2 * j0), scale, base);
        const float sxa0  = fmaxf(rawa0, 0.0f);
        const float sxb0  = rawa0 + scale;
        const int   x0a0  = (int)sxa0;
        const int   x0b0  = (int)sxb0;
        const float wxa0  = sxa0 - (float)x0a0;
        const float wxb0  = sxb0 - (float)x0b0;
        const int   c00   = x0a0 & ~1;
        const bool  pp0   = (x0a0 & 1) != 0;
        const int   q0    = (x0a0 & 1) + (x0b0 - x0a0);
        const bool  q10   = (q0 >= 1), q20 = (q0 == 2);
        const char* a0    = pbase + (size_t)c00 * 4;

        // ---- index math, slot 1 ----
        const float rawa1 = fmaf((float)(2 * j1), scale, base);
        const float sxa1  = fmaxf(rawa1, 0.0f);
        const float sxb1  = rawa1 + scale;
        const int   x0a1  = (int)sxa1;
        const int   x0b1  = (int)sxb1;
        const float wxa1  = sxa1 - (float)x0a1;
        const float wxb1  = sxb1 - (float)x0b1;
        const int   c01   = x0a1 & ~1;
        const bool  pp1   = (x0a1 & 1) != 0;
        const int   q1_   = (x0a1 & 1) + (x0b1 - x0a1);
        const bool  q11   = (q1_ >= 1), q21 = (q1_ == 2);
        const char* a1    = pbase + (size_t)c01 * 4;

        // ---- batched loads: 24 LDG.64 in flight ----
        float2 A0[P], A1[P], B0[P], B1[P];     // slot0: rows y0/y1, 2 float2 each
        float2 C0[P], C1[P], D0[P], D1[P];     // slot1
        #pragma unroll
        for (int k = 0; k < P; ++k) {
            A0[k] = *(const float2*)(a0 + k * PLB);
            A1[k] = *(const float2*)(a0 + k * PLB + 8);
            B0[k] = *(const float2*)(a0 + k * PLB + ROWB);
            B1[k] = *(const float2*)(a0 + k * PLB + ROWB + 8);
        }
        if (act1) {
            #pragma unroll
            for (int k = 0; k < P; ++k) {
                C0[k] = *(const float2*)(a1 + k * PLB);
                C1[k] = *(const float2*)(a1 + k * PLB + 8);
                D0[k] = *(const float2*)(a1 + k * PLB + ROWB);
                D1[k] = *(const float2*)(a1 + k * PLB + ROWB + 8);
            }
        }

        // ---- compute + store, slot 0 ----
        #pragma unroll
        for (int k = 0; k < P; ++k) {
            const float m0 = A0[k].x * onewy + B0[k].x * wy;
            const float m1 = A0[k].y * onewy + B0[k].y * wy;
            const float m2 = A1[k].x * onewy + B1[k].x * wy;
            const float m3 = A1[k].y * onewy + B1[k].y * wy;

            const float va_e = m0 * (1.0f - wxa0) + m1 * wxa0;
            const float va_o = m1 * (1.0f - wxa0) + m2 * wxa0;
            const float va   = pp0 ? va_o : va_e;

            float mb0 = q10 ? m1 : m0;  mb0 = q20 ? m2 : mb0;
            float mb1 = q10 ? m2 : m1;  mb1 = q20 ? m3 : mb1;
            const float vb = mb0 * (1.0f - wxb0) + mb1 * wxb0;

            *(float2*)(obase + (size_t)j0 * 8 + k * OPLB) = make_float2(va, vb);
        }

        // ---- compute + store, slot 1 ----
        if (act1) {
            #pragma unroll
            for (int k = 0; k < P; ++k) {
                const float m0 = C0[k].x * onewy + D0[k].x * wy;
                const float m1 = C0[k].y * onewy + D0[k].y * wy;
                const float m2 = C1[k].x * onewy + D1[k].x * wy;
                const float m3 = C1[k].y * onewy + D1[k].y * wy;

                const float va_e = m0 * (1.0f - wxa1) + m1 * wxa1;
                const float va_o = m1 * (1.0f - wxa1) + m2 * wxa1;
                const float va   = pp1 ? va_o : va_e;

                float mb0 = q11 ? m1 : m0;  mb0 = q21 ? m2 : mb0;
                float mb1 = q11 ? m2 : m1;  mb1 = q21 ? m3 : mb1;
                const float vb = mb0 * (1.0f - wxb1) + mb1 * wxb1;

                *(float2*)(obase + (size_t)j1 * 8 + k * OPLB) = make_float2(va, vb);
            }
        }
    }
}

extern "C" void kernel_launch(void* const* d_in, const int* in_sizes, int n_in,
                              void* d_out, int out_size)
{
    const float* x    = (const float*)d_in[0];
    const int*   cams = (const int*)  d_in[1];
    const float* rz   = (const float*)d_in[2];
    const float* yo   = (const float*)d_in[3];
    const float* xo   = (const float*)d_in[4];
    float* out = (float*)d_out;

    dim3 block(32, 8, 1);
    dim3 grid(1, S / 8, (BATCH * PLANES_PER_B) / P);
    crop_prompter_kernel<<<grid, block>>>(x, cams, rz, yo, xo, out);
}